// round 6
// baseline (speedup 1.0000x reference)
#include <cuda_runtime.h>
#include <cuda_bf16.h>
#include <cstdint>

#define NNODES 100000
#define EEDGES 1600000
#define HID    128
#define NCLS   40

// ---------------- scratch (device globals; no allocation allowed) ------------
__device__ __align__(128) __nv_bfloat16 g_h1hi[NNODES * HID];
__device__ __align__(128) __nv_bfloat16 g_h1lo[NNODES * HID];
__device__ __align__(128) __nv_bfloat16 g_h2hi[NNODES * HID];
__device__ __align__(128) __nv_bfloat16 g_h2lo[NNODES * HID];
__device__ __align__(128) __nv_bfloat16 g_wbhi[5 * HID * HID];   // [slot][n][k]
__device__ __align__(128) __nv_bfloat16 g_wblo[5 * HID * HID];
__device__ __align__(128) __nv_bfloat16 g_wchi[48 * HID];        // padded classifier W [n][k]
__device__ __align__(128) __nv_bfloat16 g_wclo[48 * HID];
__device__ int   g_outdeg[NNODES];
__device__ int   g_indeg[NNODES];
__device__ int   g_cursor[NNODES];
__device__ float g_onorm[NNODES];
__device__ float g_inorm[NNODES];
__device__ int   g_rowoff[NNODES + 1];
__device__ int   g_bsums[256];
__device__ int   g_esrc[EEDGES];

// ---------------- PTX helpers -------------------------------------------------
__device__ __forceinline__ uint32_t smem_u32(const void* p) {
    uint32_t a;
    asm("{ .reg .u64 t; cvta.to.shared.u64 t, %1; cvt.u32.u64 %0, t; }" : "=r"(a) : "l"(p));
    return a;
}

#define LDSM4(r, addr)                                                          \
    asm volatile("ldmatrix.sync.aligned.m8n8.x4.shared.b16 {%0,%1,%2,%3}, [%4];" \
        : "=r"((r)[0]), "=r"((r)[1]), "=r"((r)[2]), "=r"((r)[3]) : "r"(addr))

#define MMA16816(d, a, b0, b1)                                                  \
    asm volatile("mma.sync.aligned.m16n8k16.row.col.f32.bf16.bf16.f32 "         \
        "{%0,%1,%2,%3}, {%4,%5,%6,%7}, {%8,%9}, {%0,%1,%2,%3};"                 \
        : "+f"((d)[0]), "+f"((d)[1]), "+f"((d)[2]), "+f"((d)[3])                \
        : "r"((a)[0]), "r"((a)[1]), "r"((a)[2]), "r"((a)[3]), "r"(b0), "r"(b1))

#define CP_ASYNC16(smem_addr, gptr)                                             \
    asm volatile("cp.async.ca.shared.global [%0], [%1], 16;"                    \
        :: "r"(smem_addr), "l"(gptr))
#define CP_ASYNC16Z(smem_addr, gptr, nbytes)                                    \
    asm volatile("cp.async.ca.shared.global [%0], [%1], 16, %2;"                \
        :: "r"(smem_addr), "l"(gptr), "r"(nbytes))
#define CP_COMMIT() asm volatile("cp.async.commit_group;" ::: "memory")
#define CP_WAIT0()  asm volatile("cp.async.wait_group 0;" ::: "memory")
#define CP_WAIT1()  asm volatile("cp.async.wait_group 1;" ::: "memory")

__device__ __forceinline__ void split2(float v, __nv_bfloat16& h, __nv_bfloat16& l) {
    h = __float2bfloat16(v);
    l = __float2bfloat16(v - __bfloat162float(h));
}

// ---------------- small prep kernels ----------------------------------------
__global__ void zero_ints_kernel(int n) {
    int i = blockIdx.x * blockDim.x + threadIdx.x;
    if (i < n) { g_outdeg[i] = 0; g_indeg[i] = 0; g_cursor[i] = 0; }
}

__global__ void degree_kernel(const int* __restrict__ src,
                              const int* __restrict__ dst, int E) {
    int e = blockIdx.x * blockDim.x + threadIdx.x;
    if (e < E) {
        atomicAdd(&g_outdeg[src[e]], 1);
        atomicAdd(&g_indeg[dst[e]], 1);
    }
}

__global__ void norm_kernel(int n) {
    int i = blockIdx.x * blockDim.x + threadIdx.x;
    if (i < n) {
        g_onorm[i] = rsqrtf((float)max(g_outdeg[i], 1));
        g_inorm[i] = rsqrtf((float)max(g_indeg[i], 1));
    }
}

__global__ void scan1_kernel(int n) {
    __shared__ int s[1024];
    int tid = threadIdx.x;
    int i = blockIdx.x * 1024 + tid;
    int v = (i < n) ? g_indeg[i] : 0;
    s[tid] = v;
    __syncthreads();
    #pragma unroll
    for (int off = 1; off < 1024; off <<= 1) {
        int t = 0;
        if (tid >= off) t = s[tid - off];
        __syncthreads();
        s[tid] += t;
        __syncthreads();
    }
    if (i < n) g_rowoff[i] = s[tid] - v;
    if (tid == 1023) g_bsums[blockIdx.x] = s[1023];
}

__global__ void scan2_kernel(int nb, int n, int E) {
    if (threadIdx.x == 0 && blockIdx.x == 0) {
        int run = 0;
        for (int b = 0; b < nb; b++) { int t = g_bsums[b]; g_bsums[b] = run; run += t; }
        g_rowoff[n] = E;
    }
}

__global__ void scan3_kernel(int n) {
    int i = blockIdx.x * 1024 + threadIdx.x;
    if (i < n) g_rowoff[i] += g_bsums[blockIdx.x];
}

__global__ void fill_kernel(const int* __restrict__ src,
                            const int* __restrict__ dst, int E) {
    int e = blockIdx.x * blockDim.x + threadIdx.x;
    if (e < E) {
        int d = dst[e];
        int pos = g_rowoff[d] + atomicAdd(&g_cursor[d], 1);
        g_esrc[pos] = src[e];
    }
}

// ---------------- converters --------------------------------------------------
__global__ void convert_x_kernel(const float* __restrict__ x,
                                 __nv_bfloat16* __restrict__ hi,
                                 __nv_bfloat16* __restrict__ lo, int total) {
    int i = blockIdx.x * blockDim.x + threadIdx.x;
    if (i < total) {
        __nv_bfloat16 h, l;
        split2(x[i], h, l);
        hi[i] = h; lo[i] = l;
    }
}

// W[L][k][n] fp32 -> [L][n][k] bf16 hi/lo (transposed)
__global__ void convert_w_kernel(const float* __restrict__ W, int L,
                                 __nv_bfloat16* __restrict__ hi,
                                 __nv_bfloat16* __restrict__ lo) {
    int o = blockIdx.x * blockDim.x + threadIdx.x;
    if (o < L * HID * HID) {
        int l = o / (HID * HID);
        int r = o - l * HID * HID;
        int n = r >> 7;
        int k = r & 127;
        float v = W[l * HID * HID + k * HID + n];
        __nv_bfloat16 h, lw;
        split2(v, h, lw);
        hi[o] = h; lo[o] = lw;
    }
}

// Wc[128][40] fp32 -> [48 padded][128] bf16 hi/lo
__global__ void convert_wc_kernel(const float* __restrict__ Wc,
                                  __nv_bfloat16* __restrict__ hi,
                                  __nv_bfloat16* __restrict__ lo) {
    int o = blockIdx.x * blockDim.x + threadIdx.x;
    if (o < 48 * HID) {
        int n = o >> 7;
        int k = o & 127;
        float v = (n < NCLS) ? Wc[k * NCLS + n] : 0.f;
        __nv_bfloat16 h, lw;
        split2(v, h, lw);
        hi[o] = h; lo[o] = lw;
    }
}

// ---------------- gather: warp per dst node, split bf16 I/O -------------------
__global__ void __launch_bounds__(256)
gather_kernel(const __nv_bfloat16* __restrict__ hHi, const __nv_bfloat16* __restrict__ hLo,
              __nv_bfloat16* __restrict__ oHi, __nv_bfloat16* __restrict__ oLo, int n) {
    int gw = (blockIdx.x * blockDim.x + threadIdx.x) >> 5;
    int lane = threadIdx.x & 31;
    if (gw >= n) return;
    int e0 = g_rowoff[gw];
    int e1 = g_rowoff[gw + 1];
    float a0 = 0.f, a1 = 0.f, a2 = 0.f, a3 = 0.f;
    int e = e0;
    for (; e + 1 < e1; e += 2) {
        int s0 = g_esrc[e];
        int s1 = g_esrc[e + 1];
        float w0 = g_onorm[s0];
        float w1 = g_onorm[s1];
        uint2 uh0 = ((const uint2*)(hHi + (size_t)s0 * HID))[lane];
        uint2 ul0 = ((const uint2*)(hLo + (size_t)s0 * HID))[lane];
        uint2 uh1 = ((const uint2*)(hHi + (size_t)s1 * HID))[lane];
        uint2 ul1 = ((const uint2*)(hLo + (size_t)s1 * HID))[lane];
        float2 h00 = __bfloat1622float2(*(__nv_bfloat162*)&uh0.x);
        float2 h01 = __bfloat1622float2(*(__nv_bfloat162*)&uh0.y);
        float2 l00 = __bfloat1622float2(*(__nv_bfloat162*)&ul0.x);
        float2 l01 = __bfloat1622float2(*(__nv_bfloat162*)&ul0.y);
        a0 = fmaf(h00.x + l00.x, w0, a0); a1 = fmaf(h00.y + l00.y, w0, a1);
        a2 = fmaf(h01.x + l01.x, w0, a2); a3 = fmaf(h01.y + l01.y, w0, a3);
        float2 h10 = __bfloat1622float2(*(__nv_bfloat162*)&uh1.x);
        float2 h11 = __bfloat1622float2(*(__nv_bfloat162*)&uh1.y);
        float2 l10 = __bfloat1622float2(*(__nv_bfloat162*)&ul1.x);
        float2 l11 = __bfloat1622float2(*(__nv_bfloat162*)&ul1.y);
        a0 = fmaf(h10.x + l10.x, w1, a0); a1 = fmaf(h10.y + l10.y, w1, a1);
        a2 = fmaf(h11.x + l11.x, w1, a2); a3 = fmaf(h11.y + l11.y, w1, a3);
    }
    if (e < e1) {
        int s0 = g_esrc[e];
        float w0 = g_onorm[s0];
        uint2 uh0 = ((const uint2*)(hHi + (size_t)s0 * HID))[lane];
        uint2 ul0 = ((const uint2*)(hLo + (size_t)s0 * HID))[lane];
        float2 h00 = __bfloat1622float2(*(__nv_bfloat162*)&uh0.x);
        float2 h01 = __bfloat1622float2(*(__nv_bfloat162*)&uh0.y);
        float2 l00 = __bfloat1622float2(*(__nv_bfloat162*)&ul0.x);
        float2 l01 = __bfloat1622float2(*(__nv_bfloat162*)&ul0.y);
        a0 = fmaf(h00.x + l00.x, w0, a0); a1 = fmaf(h00.y + l00.y, w0, a1);
        a2 = fmaf(h01.x + l01.x, w0, a2); a3 = fmaf(h01.y + l01.y, w0, a3);
    }
    float inn = g_inorm[gw];
    float v0 = a0 * inn, v1 = a1 * inn, v2 = a2 * inn, v3 = a3 * inn;
    __nv_bfloat16 h0, l0, h1, l1, h2, l2, h3, l3;
    split2(v0, h0, l0); split2(v1, h1, l1); split2(v2, h2, l2); split2(v3, h3, l3);
    uint2 wh, wl;
    *(__nv_bfloat162*)&wh.x = __halves2bfloat162(h0, h1);
    *(__nv_bfloat162*)&wh.y = __halves2bfloat162(h2, h3);
    *(__nv_bfloat162*)&wl.x = __halves2bfloat162(l0, l1);
    *(__nv_bfloat162*)&wl.y = __halves2bfloat162(l2, l3);
    ((uint2*)(oHi + (size_t)gw * HID))[lane] = wh;
    ((uint2*)(oLo + (size_t)gw * HID))[lane] = wl;
}

// ---------------- HMMA GEMM: C[M,128] = A[M,128] @ W + b ---------------------
// Split-bf16, D = Ahi*Whi + Alo*Whi + Ahi*Wlo (fp32 acc). A pre-split in gmem,
// loaded via cp.async into double-buffered K=32 chunks. W hi/lo resident.
// Output written as split bf16 hi/lo. smem ~96.5KB -> 2 CTAs/SM.
#define SM_BIAS 0
#define SM_WHI  512
#define SM_WLO  (SM_WHI + 32768)
#define SM_ACH  (SM_WLO + 32768)
#define SM_TOTAL (SM_ACH + 2 * 16384)

__global__ void __launch_bounds__(256, 2)
gemm_mma_kernel(const __nv_bfloat16* __restrict__ Ahi, const __nv_bfloat16* __restrict__ Alo,
                const __nv_bfloat16* __restrict__ Whi, const __nv_bfloat16* __restrict__ Wlo,
                const float* __restrict__ bias,
                __nv_bfloat16* __restrict__ Chi, __nv_bfloat16* __restrict__ Clo,
                int M, int relu) {
    extern __shared__ char smem[];
    uint32_t sb = smem_u32(smem);
    const int tid = threadIdx.x;
    const int lane = tid & 31;
    const int wid = tid >> 5;
    const int rowBase = blockIdx.x << 7;

    // ---- W tiles via cp.async ----
    #pragma unroll
    for (int it = 0; it < 8; it++) {
        int chunk = tid + it * 256;
        int row = chunk >> 4;
        int cc = chunk & 15;
        uint32_t so = (uint32_t)(row * 256 + ((cc ^ (row & 7)) << 4));
        CP_ASYNC16(sb + SM_WHI + so, (const char*)(Whi + row * HID + cc * 8));
        CP_ASYNC16(sb + SM_WLO + so, (const char*)(Wlo + row * HID + cc * 8));
    }
    if (tid < 128) ((float*)smem)[tid] = bias[tid];
    CP_COMMIT();                                   // G0: W

    // ---- A chunk issuer: 1024 x 16B per chunk (hi 512 + lo 512), 4/thread ----
    auto issueA = [&](int c, int buf) {
        #pragma unroll
        for (int j = 0; j < 4; j++) {
            int id = tid + j * 256;                // 0..1023
            int row = id >> 3;
            int rem = id & 7;
            int s = rem & 3;                       // 16B slot within 64B half
            int part = rem >> 2;                   // 0 hi, 1 lo
            int gRow = rowBase + row;
            const __nv_bfloat16* gsrc = (part ? Alo : Ahi)
                                      + (size_t)gRow * HID + c * 32 + s * 8;
            uint32_t daddr = sb + SM_ACH + buf * 16384 + row * 128
                           + (((s + part * 4) ^ (row & 7)) << 4);
            int nb = (gRow < M) ? 16 : 0;
            CP_ASYNC16Z(daddr, (const char*)gsrc, nb);
        }
        CP_COMMIT();
    };

    issueA(0, 0);                                  // G1
    issueA(1, 1);                                  // G2

    const int warpRow = (wid & 3) * 32;
    const int warpCol = (wid >> 2) * 64;
    float acc[2][8][4];
    #pragma unroll
    for (int mi = 0; mi < 2; mi++)
        #pragma unroll
        for (int nt = 0; nt < 8; nt++)
            #pragma unroll
            for (int q = 0; q < 4; q++) acc[mi][nt][q] = 0.f;

    const int lr = (lane & 7) + (lane & 8);
    const int lk = (lane & 16) >> 1;

    #pragma unroll
    for (int c = 0; c < 4; c++) {
        if (c == 3) { CP_WAIT0(); } else { CP_WAIT1(); }
        __syncthreads();
        const int buf = c & 1;
        const uint32_t abase = sb + SM_ACH + buf * 16384;
        #pragma unroll
        for (int ks = 0; ks < 2; ks++) {
            const int kic = ks * 16 + lk;
            const int sA = kic >> 3;
            uint32_t ah[2][4], al[2][4], bh[4][4], bl[4][4];
            #pragma unroll
            for (int mi = 0; mi < 2; mi++) {
                int row = warpRow + mi * 16 + lr;
                uint32_t ad = abase + row * 128;
                LDSM4(ah[mi], ad + (((sA)     ^ (row & 7)) << 4));
                LDSM4(al[mi], ad + (((sA + 4) ^ (row & 7)) << 4));
            }
            const int kc = (c * 32 + kic) >> 3;
            #pragma unroll
            for (int nj = 0; nj < 4; nj++) {
                int row = warpCol + nj * 16 + lr;
                uint32_t bd = sb + row * 256 + ((kc ^ (row & 7)) << 4);
                LDSM4(bh[nj], bd + SM_WHI);
                LDSM4(bl[nj], bd + SM_WLO);
            }
            #pragma unroll
            for (int mi = 0; mi < 2; mi++) {
                #pragma unroll
                for (int nt = 0; nt < 8; nt++) {
                    int nj = nt >> 1, up = nt & 1;
                    MMA16816(acc[mi][nt], ah[mi], bh[nj][0 + up], bh[nj][2 + up]);
                    MMA16816(acc[mi][nt], al[mi], bh[nj][0 + up], bh[nj][2 + up]);
                    MMA16816(acc[mi][nt], ah[mi], bl[nj][0 + up], bl[nj][2 + up]);
                }
            }
        }
        if (c < 2) {
            __syncthreads();                       // all warps done reading buf
            issueA(c + 2, buf);
        }
    }

    // ---- epilogue: split fp32 -> hi/lo bf16 ----
    const int grp = lane >> 2, qid = lane & 3;
    #pragma unroll
    for (int mi = 0; mi < 2; mi++) {
        #pragma unroll
        for (int nt = 0; nt < 8; nt++) {
            int col = warpCol + nt * 8 + qid * 2;
            float b0 = ((float*)smem)[col];
            float b1 = ((float*)smem)[col + 1];
            int r0 = rowBase + warpRow + mi * 16 + grp;
            float v0 = acc[mi][nt][0] + b0, v1 = acc[mi][nt][1] + b1;
            float v2 = acc[mi][nt][2] + b0, v3 = acc[mi][nt][3] + b1;
            if (relu) {
                v0 = fmaxf(v0, 0.f); v1 = fmaxf(v1, 0.f);
                v2 = fmaxf(v2, 0.f); v3 = fmaxf(v3, 0.f);
            }
            __nv_bfloat16 h0, l0, h1, l1;
            if (r0 < M) {
                split2(v0, h0, l0); split2(v1, h1, l1);
                *(__nv_bfloat162*)(Chi + (size_t)r0 * HID + col) = __halves2bfloat162(h0, h1);
                *(__nv_bfloat162*)(Clo + (size_t)r0 * HID + col) = __halves2bfloat162(l0, l1);
            }
            if (r0 + 8 < M) {
                split2(v2, h0, l0); split2(v3, h1, l1);
                *(__nv_bfloat162*)(Chi + (size_t)(r0 + 8) * HID + col) = __halves2bfloat162(h0, h1);
                *(__nv_bfloat162*)(Clo + (size_t)(r0 + 8) * HID + col) = __halves2bfloat162(l0, l1);
            }
        }
    }
}

// ---------------- classifier HMMA: out[M,40] = A[M,128] @ Wc + bc -------------
// Block tile 128 rows x 48 cols (padded from 40). 8 warps, warp = 16 rows.
#define SMC_BC  0
#define SMC_WHI 256
#define SMC_WLO (SMC_WHI + 48 * 256)
#define SMC_ACH (SMC_WLO + 48 * 256)
#define SMC_TOTAL (SMC_ACH + 2 * 16384)

__global__ void __launch_bounds__(256)
cls_mma_kernel(const __nv_bfloat16* __restrict__ Ahi, const __nv_bfloat16* __restrict__ Alo,
               const __nv_bfloat16* __restrict__ Wchi, const __nv_bfloat16* __restrict__ Wclo,
               const float* __restrict__ bc, float* __restrict__ out, int M) {
    extern __shared__ char smem[];
    uint32_t sb = smem_u32(smem);
    const int tid = threadIdx.x;
    const int lane = tid & 31;
    const int wid = tid >> 5;
    const int rowBase = blockIdx.x << 7;

    // W tiles: 48 rows x 16 chunks x 2 tiles = 1536 ops, 6/thread
    #pragma unroll
    for (int it = 0; it < 6; it++) {
        int chunk = tid + it * 256;
        int t = (chunk >= 768);
        int cr = chunk - t * 768;
        int row = cr >> 4;
        int cc = cr & 15;
        uint32_t so = (uint32_t)(row * 256 + ((cc ^ (row & 7)) << 4));
        const __nv_bfloat16* gsrc = (t ? Wclo : Wchi) + row * HID + cc * 8;
        CP_ASYNC16(sb + (t ? SMC_WLO : SMC_WHI) + so, (const char*)gsrc);
    }
    if (tid < NCLS) ((float*)smem)[tid] = bc[tid];
    CP_COMMIT();

    auto issueA = [&](int c, int buf) {
        #pragma unroll
        for (int j = 0; j < 4; j++) {
            int id = tid + j * 256;
            int row = id >> 3;
            int rem = id & 7;
            int s = rem & 3;
            int part = rem >> 2;
            int gRow = rowBase + row;
            const __nv_bfloat16* gsrc = (part ? Alo : Ahi)
                                      + (size_t)gRow * HID + c * 32 + s * 8;
            uint32_t daddr = sb + SMC_ACH + buf * 16384 + row * 128
                           + (((s + part * 4) ^ (row & 7)) << 4);
            int nb = (gRow < M) ? 16 : 0;
            CP_ASYNC16Z(daddr, (const char*)gsrc, nb);
        }
        CP_COMMIT();
    };
    issueA(0, 0);
    issueA(1, 1);

    const int warpRow = wid * 16;
    float acc[6][4];
    #pragma unroll
    for (int nt = 0; nt < 6; nt++)
        #pragma unroll
        for (int q = 0; q < 4; q++) acc[nt][q] = 0.f;

    const int lr = (lane & 7) + (lane & 8);
    const int lk = (lane & 16) >> 1;

    #pragma unroll
    for (int c = 0; c < 4; c++) {
        if (c == 3) { CP_WAIT0(); } else { CP_WAIT1(); }
        __syncthreads();
        const int buf = c & 1;
        const uint32_t abase = sb + SMC_ACH + buf * 16384;
        #pragma unroll
        for (int ks = 0; ks < 2; ks++) {
            const int kic = ks * 16 + lk;
            const int sA = kic >> 3;
            uint32_t ah[4], al[4], bh[3][4], bl[3][4];
            {
                int row = warpRow + lr;
                uint32_t ad = abase + row * 128;
                LDSM4(ah, ad + (((sA)     ^ (row & 7)) << 4));
                LDSM4(al, ad + (((sA + 4) ^ (row & 7)) << 4));
            }
            const int kc = (c * 32 + kic) >> 3;
            #pragma unroll
            for (int nj = 0; nj < 3; nj++) {
                int row = nj * 16 + lr;
                uint32_t bd = sb + row * 256 + ((kc ^ (row & 7)) << 4);
                LDSM4(bh[nj], bd + SMC_WHI);
                LDSM4(bl[nj], bd + SMC_WLO);
            }
            #pragma unroll
            for (int nt = 0; nt < 6; nt++) {
                int nj = nt >> 1, up = nt & 1;
                MMA16816(acc[nt], ah, bh[nj][0 + up], bh[nj][2 + up]);
                MMA16816(acc[nt], al, bh[nj][0 + up], bh[nj][2 + up]);
                MMA16816(acc[nt], ah, bl[nj][0 + up], bl[nj][2 + up]);
            }
        }
        if (c < 2) {
            __syncthreads();
            issueA(c + 2, buf);
        }
    }

    const int grp = lane >> 2, qid = lane & 3;
    #pragma unroll
    for (int nt = 0; nt < 6; nt++) {
        int col = nt * 8 + qid * 2;
        if (col < NCLS) {
            float b0 = ((float*)smem)[col];
            float b1 = ((float*)smem)[col + 1];
            int r0 = rowBase + warpRow + grp;
            if (r0 < M)
                *(float2*)(out + (size_t)r0 * NCLS + col)
                    = make_float2(acc[nt][0] + b0, acc[nt][1] + b1);
            if (r0 + 8 < M)
                *(float2*)(out + (size_t)(r0 + 8) * NCLS + col)
                    = make_float2(acc[nt][2] + b0, acc[nt][3] + b1);
        }
    }
}

// ---------------- launch ------------------------------------------------------
extern "C" void kernel_launch(void* const* d_in, const int* in_sizes, int n_in,
                              void* d_out, int out_size) {
    const float* x   = (const float*)d_in[0];
    const int*   src = (const int*)  d_in[1];
    const int*   dst = (const int*)  d_in[2];
    const float* W1  = (const float*)d_in[3];
    const float* b1  = (const float*)d_in[4];
    const float* W2  = (const float*)d_in[5];
    const float* b2  = (const float*)d_in[6];
    const float* Wg  = (const float*)d_in[7];   // [3,128,128]
    const float* bg  = (const float*)d_in[8];   // [3,128]
    const float* Wc  = (const float*)d_in[9];
    const float* bc  = (const float*)d_in[10];
    float* out = (float*)d_out;

    const int N = in_sizes[0] / HID;
    const int E = in_sizes[1];

    __nv_bfloat16 *h1hi, *h1lo, *h2hi, *h2lo, *wbhi, *wblo, *wchi, *wclo;
    cudaGetSymbolAddress((void**)&h1hi, g_h1hi);
    cudaGetSymbolAddress((void**)&h1lo, g_h1lo);
    cudaGetSymbolAddress((void**)&h2hi, g_h2hi);
    cudaGetSymbolAddress((void**)&h2lo, g_h2lo);
    cudaGetSymbolAddress((void**)&wbhi, g_wbhi);
    cudaGetSymbolAddress((void**)&wblo, g_wblo);
    cudaGetSymbolAddress((void**)&wchi, g_wchi);
    cudaGetSymbolAddress((void**)&wclo, g_wclo);

    cudaFuncSetAttribute(gemm_mma_kernel,
                         cudaFuncAttributeMaxDynamicSharedMemorySize, SM_TOTAL);
    cudaFuncSetAttribute(cls_mma_kernel,
                         cudaFuncAttributeMaxDynamicSharedMemorySize, SMC_TOTAL);

    const int TB = 256;
    const int gN = (N + TB - 1) / TB;
    const int gE = (E + TB - 1) / TB;
    const int nb = (N + 1023) / 1024;
    const int gGemm = (N + 127) / 128;
    const int gGather = (N + 7) / 8;

    // Launch order: 4th launch is gemm #1 (that's the one ncu captures).
    convert_x_kernel<<<(N * HID + TB - 1) / TB, TB>>>(x, h2hi, h2lo, N * HID);                                   // 1
    convert_w_kernel<<<(1 * HID * HID + TB - 1) / TB, TB>>>(W1, 1, wbhi + 0 * HID * HID, wblo + 0 * HID * HID);  // 2
    zero_ints_kernel<<<gN, TB>>>(N);                                                                             // 3
    gemm_mma_kernel<<<gGemm, TB, SM_TOTAL>>>(h2hi, h2lo, wbhi + 0 * HID * HID, wblo + 0 * HID * HID,
                                             b1, h1hi, h1lo, N, 0);                                              // 4 <- profiled
    degree_kernel<<<gE, TB>>>(src, dst, E);
    norm_kernel<<<gN, TB>>>(N);
    scan1_kernel<<<nb, 1024>>>(N);
    scan2_kernel<<<1, 32>>>(nb, N, E);
    scan3_kernel<<<nb, 1024>>>(N);
    fill_kernel<<<gE, TB>>>(src, dst, E);
    convert_w_kernel<<<(1 * HID * HID + TB - 1) / TB, TB>>>(W2, 1, wbhi + 1 * HID * HID, wblo + 1 * HID * HID);
    convert_w_kernel<<<(3 * HID * HID + TB - 1) / TB, TB>>>(Wg, 3, wbhi + 2 * HID * HID, wblo + 2 * HID * HID);
    convert_wc_kernel<<<(48 * HID + TB - 1) / TB, TB>>>(Wc, wchi, wclo);

    gemm_mma_kernel<<<gGemm, TB, SM_TOTAL>>>(h1hi, h1lo, wbhi + 1 * HID * HID, wblo + 1 * HID * HID,
                                             b2, h2hi, h2lo, N, 0);

    gather_kernel<<<gGather, TB>>>(h2hi, h2lo, h1hi, h1lo, N);
    gemm_mma_kernel<<<gGemm, TB, SM_TOTAL>>>(h1hi, h1lo, wbhi + 2 * HID * HID, wblo + 2 * HID * HID,
                                             bg + 0 * HID, h2hi, h2lo, N, 1);

    gather_kernel<<<gGather, TB>>>(h2hi, h2lo, h1hi, h1lo, N);
    gemm_mma_kernel<<<gGemm, TB, SM_TOTAL>>>(h1hi, h1lo, wbhi + 3 * HID * HID, wblo + 3 * HID * HID,
                                             bg + 1 * HID, h2hi, h2lo, N, 1);

    gather_kernel<<<gGather, TB>>>(h2hi, h2lo, h1hi, h1lo, N);
    gemm_mma_kernel<<<gGemm, TB, SM_TOTAL>>>(h1hi, h1lo, wbhi + 4 * HID * HID, wblo + 4 * HID * HID,
                                             bg + 2 * HID, h2hi, h2lo, N, 1);

    cls_mma_kernel<<<gGemm, TB, SMC_TOTAL>>>(h2hi, h2lo, wchi, wclo, bc, out, N);
}